// round 1
// baseline (speedup 1.0000x reference)
#include <cuda_runtime.h>

// Problem constants (fixed by reference setup)
#define RQf 5.0f
#define THRESHOLDf 4.0f
#define RADIUS2f 100.0f   // (2*RQ)^2

constexpr int Q       = 960;       // 4*6*40 query points
constexpr int M       = 50000;     // terrain points
constexpr int QB      = 8;         // queries per block (register-blocked)
constexpr int NQB     = Q / QB;    // 120
constexpr int MCHUNK  = 8;         // terrain chunks (grid.y)
constexpr int CHUNK   = M / MCHUNK;// 6250
constexpr int THREADS = 256;
constexpr int NWARP   = THREADS / 32;
constexpr int BP      = 24;        // output elements (B*P)
constexpr int T       = 40;        // trajectory length per (B,P)

// Scratch partials: fully rewritten every launch -> deterministic, graph-safe.
__device__ float g_cnt[Q * MCHUNK];
__device__ float g_sum[Q * MCHUNK];

__global__ __launch_bounds__(THREADS)
void pair_kernel(const float* __restrict__ q, const float* __restrict__ terr) {
    const int qb = blockIdx.x;   // 0..NQB-1
    const int mc = blockIdx.y;   // 0..MCHUNK-1
    const int q0 = qb * QB;

    // Query coords in registers (broadcast loads, L1-cached)
    float qx[QB], qy[QB], qz[QB];
#pragma unroll
    for (int j = 0; j < QB; j++) {
        qx[j] = __ldg(q + (q0 + j) * 3 + 0);
        qy[j] = __ldg(q + (q0 + j) * 3 + 1);
        qz[j] = __ldg(q + (q0 + j) * 3 + 2);
    }

    float cnt[QB], sum[QB];
#pragma unroll
    for (int j = 0; j < QB; j++) { cnt[j] = 0.f; sum[j] = 0.f; }

    const int mstart = mc * CHUNK;
    const int mend   = mstart + CHUNK;
    for (int i = mstart + threadIdx.x; i < mend; i += THREADS) {
        const float tx = __ldg(terr + 3 * i + 0);
        const float ty = __ldg(terr + 3 * i + 1);
        const float tz = __ldg(terr + 3 * i + 2);
#pragma unroll
        for (int j = 0; j < QB; j++) {
            const float dx = qx[j] - tx;
            const float dy = qy[j] - ty;
            const float dz = qz[j] - tz;
            const float d2 = fmaf(dz, dz, fmaf(dy, dy, dx * dx));
            // Classification uses exact d2 compare (matches reference rounding);
            // approx sqrt only feeds the sum (rel err ~1e-6 << 1e-3 gate).
            float d;
            asm("sqrt.approx.f32 %0, %1;" : "=f"(d) : "f"(d2));
            if (d2 <= RADIUS2f) { cnt[j] += 1.0f; sum[j] += d; }
        }
    }

    // Intra-warp tree reduce (per query slot)
#pragma unroll
    for (int j = 0; j < QB; j++) {
#pragma unroll
        for (int off = 16; off > 0; off >>= 1) {
            cnt[j] += __shfl_down_sync(0xffffffffu, cnt[j], off);
            sum[j] += __shfl_down_sync(0xffffffffu, sum[j], off);
        }
    }

    __shared__ float s_cnt[NWARP][QB];
    __shared__ float s_sum[NWARP][QB];
    const int lane = threadIdx.x & 31;
    const int wid  = threadIdx.x >> 5;
    if (lane == 0) {
#pragma unroll
        for (int j = 0; j < QB; j++) { s_cnt[wid][j] = cnt[j]; s_sum[wid][j] = sum[j]; }
    }
    __syncthreads();
    if (threadIdx.x < QB) {
        float c = 0.f, s = 0.f;
#pragma unroll
        for (int w = 0; w < NWARP; w++) { c += s_cnt[w][threadIdx.x]; s += s_sum[w][threadIdx.x]; }
        g_cnt[(q0 + threadIdx.x) * MCHUNK + mc] = c;
        g_sum[(q0 + threadIdx.x) * MCHUNK + mc] = s;
    }
}

__global__ __launch_bounds__(64)
void finalize_kernel(float* __restrict__ out) {
    const int bp = blockIdx.x;   // 0..BP-1
    const int t  = threadIdx.x;  // 64 threads, first T active
    float pp = 0.f;
    if (t < T) {
        const int qi = bp * T + t;
        float c = 0.f, s = 0.f;
#pragma unroll
        for (int mc = 0; mc < MCHUNK; mc++) {
            c += g_cnt[qi * MCHUNK + mc];
            s += g_sum[qi * MCHUNK + mc];
        }
        if (c > 0.f) {
            const float dm = s / c;
            pp = -(dm * dm) / (RQf * RQf) + THRESHOLDf;
        }
    }
    __shared__ float sh[64];
    sh[t] = pp;
    __syncthreads();
#pragma unroll
    for (int off = 32; off > 0; off >>= 1) {
        if (t < off) sh[t] += sh[t + off];
        __syncthreads();
    }
    if (t == 0) out[bp] = sh[0];
}

extern "C" void kernel_launch(void* const* d_in, const int* in_sizes, int n_in,
                              void* d_out, int out_size) {
    // Inputs per metadata order: [traj (960*3), terrain (50000*3)].
    // Defensive: identify by size in case of reordering.
    const float* qptr = (const float*)d_in[0];
    const float* tptr = (const float*)d_in[1];
    if (n_in >= 2 && in_sizes[0] == M * 3 && in_sizes[1] == Q * 3) {
        const float* tmp = qptr; qptr = tptr; tptr = tmp;
    }
    float* out = (float*)d_out;

    dim3 grid(NQB, MCHUNK);
    pair_kernel<<<grid, THREADS>>>(qptr, tptr);
    finalize_kernel<<<BP, 64>>>(out);
}